// round 2
// baseline (speedup 1.0000x reference)
#include <cuda_runtime.h>
#include <cuda_bf16.h>

// ---------------------------------------------------------------------------
// Problem constants
// ---------------------------------------------------------------------------
#define N_PIX   131072      // 16 * 8192 pixels
#define W_PIX   8192
#define EPS_BN  1e-5f

// ---------------------------------------------------------------------------
// Device scratch (static; no cudaMalloc allowed)
// ---------------------------------------------------------------------------
__device__ float g_cat[256 * N_PIX];   // rows 0..127 = r, rows 128..255 = h (channel-major)
__device__ float g_x2[128 * N_PIX];    // lrelu(cl2 . h)                     (channel-major)
__device__ int   g_inds[N_PIX];        // argmax class index per pixel
__device__ float g_w2cat[256 * 256];   // W2cat[s*32+o][f] = w2[s][f][o]

__device__ __forceinline__ float lrelu_f(float v) { return v >= 0.f ? v : 0.01f * v; }

// ---------------------------------------------------------------------------
// Build W2cat from w2 (8,256,32)
// ---------------------------------------------------------------------------
__global__ void prep_w2(const float* __restrict__ w2, float* __restrict__ w2cat) {
    int idx = blockIdx.x * 256 + threadIdx.x;   // 0..65535
    int so = idx >> 8;          // s*32 + o
    int f  = idx & 255;
    int s  = so >> 5;
    int o  = so & 31;
    w2cat[so * 256 + f] = w2[(s * 256 + f) * 32 + o];
}

// ---------------------------------------------------------------------------
// Register-tiled SGEMM core, 128 out x 128 px tile, BK=16, 256 threads,
// 8x8 accumulators per thread.
//
// MODE 0: channel-major store  OUT[(o0+o)*N_PIX + n] , optional BN + lrelu
// MODE 2: fused argmax over 128 channels -> indsOut[n], plus mask channel
//         (row 128 of W) -> maskOut[n]
// MODE 3: y_all GEMM (K=256) with fused super-select + w3 dot + b3 ->
//         x_real written directly to xrealOut[n]
// XIN  : X is x_in with layout [b][c][w] (k-stride 8192, batch-blocked);
//        otherwise channel-major scratch (k-stride N_PIX)
// ---------------------------------------------------------------------------
template<int MODE, bool XIN, bool BN, bool LRELU>
__global__ __launch_bounds__(256, 2) void gemm_k(
    const float* __restrict__ W, int K,
    const float* __restrict__ X,
    const float* __restrict__ bias,
    const float* __restrict__ bng, const float* __restrict__ bnb,
    const float* __restrict__ bnm, const float* __restrict__ bnv,
    float* __restrict__ outP,          // MODE0: activations; MODE2: mask; MODE3: x_real
    int* __restrict__ indsIO,          // MODE2: out; MODE3: in
    const float* __restrict__ w3,      // MODE3
    const float* __restrict__ b3)      // MODE3
{
    __shared__ float sX[16][128];
    __shared__ float sW[16][128];

    const int tid = threadIdx.x;
    const int rg = tid >> 4;          // 0..15 : out-row group (8 channels)
    const int cg = tid & 15;          // 0..15 : pixel group   (8 pixels)
    const int n0 = blockIdx.x * 128;
    const int o0 = blockIdx.y * 128;

    const int xstride = XIN ? W_PIX : N_PIX;
    const int xbase   = XIN ? ((n0 >> 13) * (128 * W_PIX) + (n0 & (W_PIX - 1))) : n0;

    // smem load assignments
    const int lr = tid >> 4;              // X: k row within chunk
    const int lc = (tid & 15) * 8;        // X: col
    const int wo = tid & 127;             // W: out index within tile
    const int wk = (tid >> 7) * 8;        // W: k offset within chunk

    float acc[8][8];
#pragma unroll
    for (int i = 0; i < 8; i++)
#pragma unroll
        for (int j = 0; j < 8; j++) acc[i][j] = 0.f;

    // MODE2 extras: mask-channel weights + accumulator
    float maskAcc = 0.f;
    __shared__ float swm[128];
    // MODE3 extras: per-pixel reduction + class indices
    __shared__ float sRed[128];
    __shared__ int   sInds[128];
    if (MODE == 2) {
        if (tid < 128) swm[tid] = W[128 * 128 + tid];
    }
    if (MODE == 3) {
        if (tid < 128) {
            sRed[tid]  = 0.f;
            sInds[tid] = indsIO[n0 + tid];
        }
    }

    for (int k0 = 0; k0 < K; k0 += 16) {
        // stage global loads in registers
        const float* xg = X + xbase + (k0 + lr) * xstride + lc;
        float4 xv0 = *(const float4*)(xg);
        float4 xv1 = *(const float4*)(xg + 4);
        const float* wg = W + (o0 + wo) * K + k0 + wk;
        float4 wv0 = *(const float4*)(wg);
        float4 wv1 = *(const float4*)(wg + 4);

        __syncthreads();   // previous iteration's smem reads complete
        *(float4*)&sX[lr][lc]     = xv0;
        *(float4*)&sX[lr][lc + 4] = xv1;
        sW[wk + 0][wo] = wv0.x; sW[wk + 1][wo] = wv0.y;
        sW[wk + 2][wo] = wv0.z; sW[wk + 3][wo] = wv0.w;
        sW[wk + 4][wo] = wv1.x; sW[wk + 5][wo] = wv1.y;
        sW[wk + 6][wo] = wv1.z; sW[wk + 7][wo] = wv1.w;
        __syncthreads();

#pragma unroll
        for (int kk = 0; kk < 16; kk++) {
            float4 xa = *(const float4*)&sX[kk][cg * 8];
            float4 xb = *(const float4*)&sX[kk][cg * 8 + 4];
            float4 wa = *(const float4*)&sW[kk][rg * 8];
            float4 wb = *(const float4*)&sW[kk][rg * 8 + 4];
            float xr[8] = {xa.x, xa.y, xa.z, xa.w, xb.x, xb.y, xb.z, xb.w};
            float wr[8] = {wa.x, wa.y, wa.z, wa.w, wb.x, wb.y, wb.z, wb.w};
#pragma unroll
            for (int i = 0; i < 8; i++)
#pragma unroll
                for (int j = 0; j < 8; j++)
                    acc[i][j] = fmaf(wr[i], xr[j], acc[i][j]);
        }

        if (MODE == 2) {
            // mask channel: threads 0..127 accumulate w_mask . x2 for pixel tid
            if (tid < 128) {
#pragma unroll
                for (int kk = 0; kk < 16; kk++)
                    maskAcc = fmaf(swm[k0 + kk], sX[kk][tid], maskAcc);
            }
        }
    }

    // per-channel alpha/beta
    float al[8], be[8];
#pragma unroll
    for (int i = 0; i < 8; i++) {
        int o = o0 + rg * 8 + i;
        float b = bias ? bias[o] : 0.f;
        if (BN) {
            float sc = bng[o] * rsqrtf(bnv[o] + EPS_BN);
            al[i] = sc;
            be[i] = (b - bnm[o]) * sc + bnb[o];
        } else {
            al[i] = 1.f;
            be[i] = b;
        }
    }

    if (MODE == 2) {
        // fused argmax (first-max-index semantics); reuse sX/sW as reduction space
        __syncthreads();
        float (*redv)[128] = sX;
        int   (*redi)[128] = (int (*)[128])sW;
#pragma unroll
        for (int j = 0; j < 8; j++) {
            int px = cg * 8 + j;
            float bv = -3.4e38f;
            int bi = 0;
#pragma unroll
            for (int i = 0; i < 8; i++) {
                float v = fmaf(al[i], acc[i][j], be[i]);
                if (v > bv) { bv = v; bi = rg * 8 + i; }
            }
            redv[rg][px] = bv;
            redi[rg][px] = bi;
        }
        __syncthreads();
        if (tid < 128) {
            float bv = redv[0][tid];
            int bi = redi[0][tid];
#pragma unroll
            for (int g = 1; g < 16; g++) {
                float v = redv[g][tid];
                if (v > bv) { bv = v; bi = redi[g][tid]; }
            }
            indsIO[n0 + tid] = bi;
            // mask = lrelu(w_mask . x2 + b_mask)
            outP[n0 + tid] = lrelu_f(maskAcc + bias[128]);
        }
        return;
    }

    if (MODE == 3) {
        // fused super-select + regression dot
        // thread (rg,cg) holds channels c0..c0+7 (c0 = o0+rg*8) for 8 pixels
        const int c0 = o0 + rg * 8;
#pragma unroll
        for (int j = 0; j < 8; j++) {
            int px = cg * 8 + j;
            int ind = sInds[px];
            int s = ind >> 4;                 // super index, CLASS_FACTOR=16
            if ((c0 >> 5) == s) {             // this thread's 8 channels are in [s*32, s*32+32)
                const float* wrow = w3 + ind * 32 + (c0 - s * 32);
                float part = 0.f;
#pragma unroll
                for (int i = 0; i < 8; i++) {
                    float y = lrelu_f(fmaf(al[i], acc[i][j], be[i]));
                    part = fmaf(y, wrow[i], part);
                }
                atomicAdd(&sRed[px], part);
            }
        }
        __syncthreads();
        if (tid < 128) {
            int ind = sInds[tid];
            // block with o0=0 owns supers 0..3 (ind<64), o0=128 owns 4..7
            if ((ind >= 64) == (o0 == 128)) {
                float reg = sRed[tid] + b3[ind];
                outP[n0 + tid] = ((float)ind + reg) * (1.0f / 128.0f);
            }
        }
        return;
    }

    // MODE 0: channel-major store
#pragma unroll
    for (int i = 0; i < 8; i++) {
        float* p = outP + (size_t)(o0 + rg * 8 + i) * N_PIX + n0 + cg * 8;
        float v[8];
#pragma unroll
        for (int j = 0; j < 8; j++) {
            float t = fmaf(al[i], acc[i][j], be[i]);
            v[j] = LRELU ? lrelu_f(t) : t;
        }
        *(float4*)(p)     = make_float4(v[0], v[1], v[2], v[3]);
        *(float4*)(p + 4) = make_float4(v[4], v[5], v[6], v[7]);
    }
}

// ---------------------------------------------------------------------------
// Launch
// ---------------------------------------------------------------------------
extern "C" void kernel_launch(void* const* d_in, const int* in_sizes, int n_in,
                              void* d_out, int out_size)
{
    const float* x_in     = (const float*)d_in[0];
    const float* cl1_w    = (const float*)d_in[1];
    const float* cl1_b    = (const float*)d_in[2];
    const float* cl1_bn_g = (const float*)d_in[3];
    const float* cl1_bn_b = (const float*)d_in[4];
    const float* cl1_bn_m = (const float*)d_in[5];
    const float* cl1_bn_v = (const float*)d_in[6];
    const float* cl2_w    = (const float*)d_in[7];
    const float* cl2_b    = (const float*)d_in[8];
    const float* cl3_w    = (const float*)d_in[9];
    const float* cl3_b    = (const float*)d_in[10];
    const float* reg1_w   = (const float*)d_in[11];
    const float* reg1_b   = (const float*)d_in[12];
    const float* reg1_bn_g= (const float*)d_in[13];
    const float* reg1_bn_b= (const float*)d_in[14];
    const float* reg1_bn_m= (const float*)d_in[15];
    const float* reg1_bn_v= (const float*)d_in[16];
    const float* w2       = (const float*)d_in[17];
    const float* b2       = (const float*)d_in[18];
    const float* w3       = (const float*)d_in[19];
    const float* b3       = (const float*)d_in[20];

    float* out = (float*)d_out;          // [0..N) x_real, [N..2N) mask

    float *cat, *x2, *w2cat;
    int* inds;
    cudaGetSymbolAddress((void**)&cat,   g_cat);
    cudaGetSymbolAddress((void**)&x2,    g_x2);
    cudaGetSymbolAddress((void**)&w2cat, g_w2cat);
    cudaGetSymbolAddress((void**)&inds,  g_inds);

    const dim3 blk(256);
    const dim3 g1(N_PIX / 128, 1);

    // Build combined super-class weight matrix [256][256]
    prep_w2<<<256, blk>>>(w2, w2cat);

    // h = lrelu(bn(cl1_w . x))  -> cat rows 128..255
    gemm_k<0, true, true, true><<<g1, blk>>>(cl1_w, 128, x_in, cl1_b,
        cl1_bn_g, cl1_bn_b, cl1_bn_m, cl1_bn_v,
        cat + (size_t)128 * N_PIX, nullptr, nullptr, nullptr);

    // r = lrelu(bn(reg1_w . x)) -> cat rows 0..127
    gemm_k<0, true, true, true><<<g1, blk>>>(reg1_w, 128, x_in, reg1_b,
        reg1_bn_g, reg1_bn_b, reg1_bn_m, reg1_bn_v,
        cat, nullptr, nullptr, nullptr);

    // x2 = lrelu(cl2_w . h)
    gemm_k<0, false, false, true><<<g1, blk>>>(cl2_w, 128, cat + (size_t)128 * N_PIX, cl2_b,
        nullptr, nullptr, nullptr, nullptr,
        x2, nullptr, nullptr, nullptr);

    // logits = cl3_w[0:128] . x2 with fused argmax -> inds, and mask channel -> out[N..2N)
    gemm_k<2, false, false, false><<<g1, blk>>>(cl3_w, 128, x2, cl3_b,
        nullptr, nullptr, nullptr, nullptr,
        out + N_PIX, inds, nullptr, nullptr);

    // y_all = lrelu(W2cat . cat + b2) with fused super-select + w3 dot -> x_real
    {
        dim3 g6(N_PIX / 128, 2);
        gemm_k<3, false, false, true><<<g6, blk>>>(w2cat, 256, cat, b2,
            nullptr, nullptr, nullptr, nullptr,
            out, inds, w3, b3);
    }
}

// round 4
// speedup vs baseline: 1.7033x; 1.7033x over previous
#include <cuda_runtime.h>
#include <cuda_bf16.h>
#include <cstdint>

// ---------------------------------------------------------------------------
// Problem constants
// ---------------------------------------------------------------------------
#define N_PIX   131072      // 16 * 8192 pixels
#define W_PIX   8192
#define EPS_BN  1e-5f

// ---------------------------------------------------------------------------
// Device scratch (static; no cudaMalloc allowed)
// ---------------------------------------------------------------------------
__device__ float          g_h[128 * N_PIX];            // lrelu(bn(cl1.x)) channel-major
__device__ float          g_x2[128 * N_PIX];           // lrelu(cl2.h)     channel-major
__device__ __nv_bfloat16  g_catT[(size_t)N_PIX * 256]; // pixel-major [n][0:128]=r [128:256]=h
__device__ __nv_bfloat16  g_w2b[256 * 256];            // bf16 W2cat[s*32+o][f]
__device__ int            g_inds[N_PIX];

__device__ __forceinline__ float lrelu_f(float v) { return v >= 0.f ? v : 0.01f * v; }

__device__ __forceinline__ uint32_t smem_u32(const void* p) {
    uint32_t a;
    asm("{ .reg .u64 t; cvta.to.shared.u64 t, %1; cvt.u32.u64 %0, t; }" : "=r"(a) : "l"(p));
    return a;
}

#define CP_ASYNC16(dst, src) \
    asm volatile("cp.async.cg.shared.global [%0], [%1], 16;" :: "r"(dst), "l"(src) : "memory")
#define CP_COMMIT()  asm volatile("cp.async.commit_group;" ::: "memory")
#define CP_WAIT0()   asm volatile("cp.async.wait_group 0;" ::: "memory")

#define LDSM_X4(r, addr) \
    asm volatile("ldmatrix.sync.aligned.m8n8.x4.shared.b16 {%0,%1,%2,%3}, [%4];" \
        : "=r"((r)[0]), "=r"((r)[1]), "=r"((r)[2]), "=r"((r)[3]) : "r"(addr))
#define LDSM_X2(r, addr) \
    asm volatile("ldmatrix.sync.aligned.m8n8.x2.shared.b16 {%0,%1}, [%2];" \
        : "=r"((r)[0]), "=r"((r)[1]) : "r"(addr))
#define MMA16816(d, a, b) \
    asm volatile("mma.sync.aligned.m16n8k16.row.col.f32.bf16.bf16.f32 " \
        "{%0,%1,%2,%3},{%4,%5,%6,%7},{%8,%9},{%0,%1,%2,%3};" \
        : "+f"((d)[0]), "+f"((d)[1]), "+f"((d)[2]), "+f"((d)[3]) \
        : "r"((a)[0]), "r"((a)[1]), "r"((a)[2]), "r"((a)[3]), "r"((b)[0]), "r"((b)[1]))

// ---------------------------------------------------------------------------
// prep: build bf16 W2cat[s*32+o][f] = w2[s][f][o]
// ---------------------------------------------------------------------------
__global__ void prep_w2(const float* __restrict__ w2, __nv_bfloat16* __restrict__ w2b) {
    int idx = blockIdx.x * 256 + threadIdx.x;   // 0..65535
    int so = idx >> 8;
    int f  = idx & 255;
    int s  = so >> 5;
    int o  = so & 31;
    w2b[so * 256 + f] = __float2bfloat16(w2[(s * 256 + f) * 32 + o]);
}

// ---------------------------------------------------------------------------
// fp32 register-tiled GEMM, 128 out x 128 px tile, BK=16, 256 threads.
// Thread pixel map: j<4 -> cg*4+j ; j>=4 -> 64+cg*4+(j-4)  (conflict-free LDS)
// MODE 0: store fp32 (channel-major) and/or bf16 catT (pixel-major at bfOff)
// MODE 2: fused argmax -> indsOut, mask channel (row 128 of W) -> maskOut
// ---------------------------------------------------------------------------
template<int MODE, bool XIN, bool BN>
__global__ __launch_bounds__(256, 2) void gemm_k(
    const float* __restrict__ W, int K,
    const float* __restrict__ X,
    const float* __restrict__ bias,
    const float* __restrict__ bng, const float* __restrict__ bnb,
    const float* __restrict__ bnm, const float* __restrict__ bnv,
    float* __restrict__ outF32,
    __nv_bfloat16* __restrict__ outBf, int bfOff,
    int* __restrict__ indsOut,
    float* __restrict__ maskOut)
{
    __shared__ float sX[16][128];
    __shared__ float sW[16][128];

    const int tid = threadIdx.x;
    const int rg = tid >> 4;          // channel group (8 channels)
    const int cg = tid & 15;          // pixel group
    const int n0 = blockIdx.x * 128;

    const int xstride = XIN ? W_PIX : N_PIX;
    const int xbase   = XIN ? ((n0 >> 13) * (128 * W_PIX) + (n0 & (W_PIX - 1))) : n0;

    const int lr = tid >> 4;
    const int lc = (tid & 15) * 8;
    const int wo = tid & 127;
    const int wk = (tid >> 7) * 8;

    float acc[8][8];
#pragma unroll
    for (int i = 0; i < 8; i++)
#pragma unroll
        for (int j = 0; j < 8; j++) acc[i][j] = 0.f;

    float maskAcc = 0.f;
    __shared__ float swm[128];
    if (MODE == 2) {
        if (tid < 128) swm[tid] = W[128 * 128 + tid];
    }

    for (int k0 = 0; k0 < K; k0 += 16) {
        const float* xg = X + xbase + (k0 + lr) * xstride + lc;
        float4 xv0 = *(const float4*)(xg);
        float4 xv1 = *(const float4*)(xg + 4);
        const float* wg = W + wo * K + k0 + wk;
        float4 wv0 = *(const float4*)(wg);
        float4 wv1 = *(const float4*)(wg + 4);

        __syncthreads();
        *(float4*)&sX[lr][lc]     = xv0;
        *(float4*)&sX[lr][lc + 4] = xv1;
        sW[wk + 0][wo] = wv0.x; sW[wk + 1][wo] = wv0.y;
        sW[wk + 2][wo] = wv0.z; sW[wk + 3][wo] = wv0.w;
        sW[wk + 4][wo] = wv1.x; sW[wk + 5][wo] = wv1.y;
        sW[wk + 6][wo] = wv1.z; sW[wk + 7][wo] = wv1.w;
        __syncthreads();

#pragma unroll
        for (int kk = 0; kk < 16; kk++) {
            float4 xa = *(const float4*)&sX[kk][cg * 4];        // contiguous across lanes
            float4 xb = *(const float4*)&sX[kk][64 + cg * 4];   // contiguous across lanes
            float4 wa = *(const float4*)&sW[kk][rg * 8];
            float4 wb = *(const float4*)&sW[kk][rg * 8 + 4];
            float xr[8] = {xa.x, xa.y, xa.z, xa.w, xb.x, xb.y, xb.z, xb.w};
            float wr[8] = {wa.x, wa.y, wa.z, wa.w, wb.x, wb.y, wb.z, wb.w};
#pragma unroll
            for (int i = 0; i < 8; i++)
#pragma unroll
                for (int j = 0; j < 8; j++)
                    acc[i][j] = fmaf(wr[i], xr[j], acc[i][j]);
        }

        if (MODE == 2) {
            if (tid < 128) {
#pragma unroll
                for (int kk = 0; kk < 16; kk++)
                    maskAcc = fmaf(swm[k0 + kk], sX[kk][tid], maskAcc);
            }
        }
    }

    float al[8], be[8];
#pragma unroll
    for (int i = 0; i < 8; i++) {
        int o = rg * 8 + i;
        float b = bias ? bias[o] : 0.f;
        if (BN) {
            float sc = bng[o] * rsqrtf(bnv[o] + EPS_BN);
            al[i] = sc;
            be[i] = (b - bnm[o]) * sc + bnb[o];
        } else {
            al[i] = 1.f;
            be[i] = b;
        }
    }

    if (MODE == 2) {
        __syncthreads();
        float (*redv)[128] = sX;
        int   (*redi)[128] = (int (*)[128])sW;
#pragma unroll
        for (int j = 0; j < 8; j++) {
            int px = (j < 4) ? (cg * 4 + j) : (64 + cg * 4 + j - 4);
            float bv = -3.4e38f;
            int bi = 0;
#pragma unroll
            for (int i = 0; i < 8; i++) {
                float v = fmaf(al[i], acc[i][j], be[i]);
                if (v > bv) { bv = v; bi = rg * 8 + i; }
            }
            redv[rg][px] = bv;
            redi[rg][px] = bi;
        }
        __syncthreads();
        if (tid < 128) {
            float bv = redv[0][tid];
            int bi = redi[0][tid];
#pragma unroll
            for (int g = 1; g < 16; g++) {
                float v = redv[g][tid];
                if (v > bv) { bv = v; bi = redi[g][tid]; }
            }
            indsOut[n0 + tid] = bi;
            maskOut[n0 + tid] = lrelu_f(maskAcc + bias[128]);
        }
        return;
    }

    // MODE 0
    if (outF32) {
#pragma unroll
        for (int i = 0; i < 8; i++) {
            float* p = outF32 + (size_t)(rg * 8 + i) * N_PIX + n0;
            float v[8];
#pragma unroll
            for (int j = 0; j < 8; j++) v[j] = lrelu_f(fmaf(al[i], acc[i][j], be[i]));
            *(float4*)(p + cg * 4)      = make_float4(v[0], v[1], v[2], v[3]);
            *(float4*)(p + 64 + cg * 4) = make_float4(v[4], v[5], v[6], v[7]);
        }
    }
    if (outBf) {
        const int c0 = rg * 8;
#pragma unroll
        for (int j = 0; j < 8; j++) {
            int px = (j < 4) ? (cg * 4 + j) : (64 + cg * 4 + j - 4);
            float v[8];
#pragma unroll
            for (int i = 0; i < 8; i++) v[i] = lrelu_f(fmaf(al[i], acc[i][j], be[i]));
            __nv_bfloat162 p0 = __floats2bfloat162_rn(v[0], v[1]);
            __nv_bfloat162 p1 = __floats2bfloat162_rn(v[2], v[3]);
            __nv_bfloat162 p2 = __floats2bfloat162_rn(v[4], v[5]);
            __nv_bfloat162 p3 = __floats2bfloat162_rn(v[6], v[7]);
            uint4 pk = make_uint4(*(uint32_t*)&p0, *(uint32_t*)&p1,
                                  *(uint32_t*)&p2, *(uint32_t*)&p3);
            *(uint4*)(outBf + (size_t)(n0 + px) * 256 + bfOff + c0) = pk;
        }
    }
}

// ---------------------------------------------------------------------------
// y_all via warp-level bf16 mma.sync (sm_100-safe HMMA path)
// Block: 128 px x 256 out, 512 threads = 16 warps (4x4), warp tile 32px x 64out.
// K=256 in 8 cp.async double-buffered stages of BK=32.
// Smem rows padded to 40 halves (80B) -> conflict-free ldmatrix.
// Fused epilogue: per-pixel super select, lrelu(+b2), dot w3, +b3 -> x_real.
// ---------------------------------------------------------------------------
#define YA_STRIDE 40                       // halves per smem row
#define YA_SA_OFF 0                        // 2*128*40*2  = 20480
#define YA_SB_OFF 20480                    // 2*256*40*2  = 40960
#define YA_SI_OFF 61440                    // inds 128*4  = 512
#define YA_SR_OFF 61952                    // red  128*4  = 512
#define YA_SW3_OFF 62464                   // w3   128*32*4 = 16384
#define YA_SB2_OFF 78848                   // b2   256*4  = 1024
#define YA_SMEM_TOTAL 79872

__global__ __launch_bounds__(512, 1) void yall_mma(
    const __nv_bfloat16* __restrict__ catT,
    const __nv_bfloat16* __restrict__ w2b,
    const float* __restrict__ b2,
    const int* __restrict__ inds,
    const float* __restrict__ w3,
    const float* __restrict__ b3,
    float* __restrict__ outX)
{
    extern __shared__ char sm[];
    __nv_bfloat16* sA = (__nv_bfloat16*)(sm + YA_SA_OFF);
    __nv_bfloat16* sB = (__nv_bfloat16*)(sm + YA_SB_OFF);
    int*   sInds = (int*)(sm + YA_SI_OFF);
    float* sRed  = (float*)(sm + YA_SR_OFF);
    float* sW3   = (float*)(sm + YA_SW3_OFF);
    float* sB2   = (float*)(sm + YA_SB2_OFF);

    const int tid  = threadIdx.x;
    const int wid  = tid >> 5;
    const int lane = tid & 31;
    const int mr   = wid >> 2;        // 0..3 : pixel band (32 px)
    const int nc   = wid & 3;         // 0..3 : out band (64 outs)
    const int n0   = blockIdx.x * 128;

    const uint32_t sAu = smem_u32(sA);
    const uint32_t sBu = smem_u32(sB);

    if (tid < 128) { sInds[tid] = inds[n0 + tid]; sRed[tid] = 0.f; }
    if (tid < 256) sB2[tid] = b2[tid];
    __syncthreads();
    {   // gather w3 rows for this tile's pixels
        int px = tid >> 2, q = tid & 3;
        int ind = sInds[px];
        *(float4*)&sW3[px * 32 + q * 8]     = *(const float4*)&w3[ind * 32 + q * 8];
        *(float4*)&sW3[px * 32 + q * 8 + 4] = *(const float4*)&w3[ind * 32 + q * 8 + 4];
    }

    // stage loaders: A 128x32 (512 x 16B), B 256x32 (1024 x 16B)
    const int aRow = tid >> 2, aSeg = tid & 3;
    auto loadStage = [&](int ks, int buf) {
        int k0 = ks * 32;
        CP_ASYNC16(sAu + ((buf * 128 + aRow) * YA_STRIDE + aSeg * 8) * 2,
                   catT + (size_t)(n0 + aRow) * 256 + k0 + aSeg * 8);
#pragma unroll
        for (int i = 0; i < 2; i++) {
            int idx = tid + i * 512;
            int row = idx >> 2, seg = idx & 3;
            CP_ASYNC16(sBu + ((buf * 256 + row) * YA_STRIDE + seg * 8) * 2,
                       w2b + row * 256 + k0 + seg * 8);
        }
    };

    float acc[2][8][4];
#pragma unroll
    for (int mt = 0; mt < 2; mt++)
#pragma unroll
        for (int nt = 0; nt < 8; nt++)
#pragma unroll
            for (int q = 0; q < 4; q++) acc[mt][nt][q] = 0.f;

    loadStage(0, 0);
    CP_COMMIT();

    // per-lane ldmatrix address components (bytes)
    const uint32_t aLane = (uint32_t)((lane & 15) * YA_STRIDE + (lane >> 4) * 8) * 2;
    const uint32_t bLane = (uint32_t)((lane & 7) * YA_STRIDE + ((lane >> 3) & 1) * 8) * 2;

#pragma unroll 1
    for (int ks = 0; ks < 8; ks++) {
        int buf = ks & 1;
        CP_WAIT0();
        __syncthreads();
        if (ks < 7) { loadStage(ks + 1, buf ^ 1); CP_COMMIT(); }

        uint32_t aBase = sAu + (uint32_t)((buf * 128 + mr * 32) * YA_STRIDE) * 2 + aLane;
        uint32_t bBase = sBu + (uint32_t)((buf * 256 + nc * 64) * YA_STRIDE) * 2 + bLane;
#pragma unroll
        for (int kf = 0; kf < 2; kf++) {
            uint32_t a[2][4];
#pragma unroll
            for (int mt = 0; mt < 2; mt++)
                LDSM_X4(a[mt], aBase + (uint32_t)(mt * 16 * YA_STRIDE + kf * 16) * 2);
            uint32_t bfr[8][2];
#pragma unroll
            for (int nt = 0; nt < 8; nt++)
                LDSM_X2(bfr[nt], bBase + (uint32_t)(nt * 8 * YA_STRIDE + kf * 16) * 2);
#pragma unroll
            for (int mt = 0; mt < 2; mt++)
#pragma unroll
                for (int nt = 0; nt < 8; nt++)
                    MMA16816(acc[mt][nt], a[mt], bfr[nt]);
        }
    }

    // fused epilogue: super-select + w3 dot, smem atomic reduction per pixel
    const int g = lane >> 2, tc = lane & 3;
#pragma unroll
    for (int mt = 0; mt < 2; mt++) {
#pragma unroll
        for (int rr = 0; rr < 2; rr++) {
            int px = mr * 32 + mt * 16 + g + rr * 8;
            int ind = sInds[px];
            int s = ind >> 4;                 // CLASS_FACTOR = 16
            if ((s >> 1) == nc) {
                int sl = s & 1;
                float part = 0.f;
#pragma unroll
                for (int t = 0; t < 4; t++) {
                    int nt = sl * 4 + t;
#pragma unroll
                    for (int cc = 0; cc < 2; cc++) {
                        int ob  = nt * 8 + tc * 2 + cc;      // out within 64-band
                        int out = nc * 64 + ob;              // global out = s*32 + orel
                        int orel = ob - sl * 32;
                        float y = lrelu_f(acc[mt][nt][rr * 2 + cc] + sB2[out]);
                        part = fmaf(y, sW3[px * 32 + orel], part);
                    }
                }
                atomicAdd(&sRed[px], part);
            }
        }
    }
    __syncthreads();
    if (tid < 128) {
        int ind = sInds[tid];
        outX[n0 + tid] = ((float)ind + sRed[tid] + b3[ind]) * (1.0f / 128.0f);
    }
}

// ---------------------------------------------------------------------------
// Launch
// ---------------------------------------------------------------------------
extern "C" void kernel_launch(void* const* d_in, const int* in_sizes, int n_in,
                              void* d_out, int out_size)
{
    const float* x_in     = (const float*)d_in[0];
    const float* cl1_w    = (const float*)d_in[1];
    const float* cl1_b    = (const float*)d_in[2];
    const float* cl1_bn_g = (const float*)d_in[3];
    const float* cl1_bn_b = (const float*)d_in[4];
    const float* cl1_bn_m = (const float*)d_in[5];
    const float* cl1_bn_v = (const float*)d_in[6];
    const float* cl2_w    = (const float*)d_in[7];
    const float* cl2_b    = (const float*)d_in[8];
    const float* cl3_w    = (const float*)d_in[9];
    const float* cl3_b    = (const float*)d_in[10];
    const float* reg1_w   = (const float*)d_in[11];
    const float* reg1_b   = (const float*)d_in[12];
    const float* reg1_bn_g= (const float*)d_in[13];
    const float* reg1_bn_b= (const float*)d_in[14];
    const float* reg1_bn_m= (const float*)d_in[15];
    const float* reg1_bn_v= (const float*)d_in[16];
    const float* w2       = (const float*)d_in[17];
    const float* b2       = (const float*)d_in[18];
    const float* w3       = (const float*)d_in[19];
    const float* b3       = (const float*)d_in[20];

    float* out = (float*)d_out;          // [0..N) x_real, [N..2N) mask

    float *h, *x2;
    __nv_bfloat16 *catT, *w2b;
    int* inds;
    cudaGetSymbolAddress((void**)&h,    g_h);
    cudaGetSymbolAddress((void**)&x2,   g_x2);
    cudaGetSymbolAddress((void**)&catT, g_catT);
    cudaGetSymbolAddress((void**)&w2b,  g_w2b);
    cudaGetSymbolAddress((void**)&inds, g_inds);

    cudaFuncSetAttribute(yall_mma, cudaFuncAttributeMaxDynamicSharedMemorySize,
                         YA_SMEM_TOTAL);

    const dim3 blk(256);
    const dim3 g1(N_PIX / 128, 1);

    // W2cat -> bf16
    prep_w2<<<256, blk>>>(w2, w2b);

    // h = lrelu(bn(cl1_w . x)) -> fp32 h + bf16 catT[:,128:256]
    gemm_k<0, true, true><<<g1, blk>>>(cl1_w, 128, x_in, cl1_b,
        cl1_bn_g, cl1_bn_b, cl1_bn_m, cl1_bn_v,
        h, catT, 128, nullptr, nullptr);

    // r = lrelu(bn(reg1_w . x)) -> bf16 catT[:,0:128] only
    gemm_k<0, true, true><<<g1, blk>>>(reg1_w, 128, x_in, reg1_b,
        reg1_bn_g, reg1_bn_b, reg1_bn_m, reg1_bn_v,
        nullptr, catT, 0, nullptr, nullptr);

    // x2 = lrelu(cl2_w . h)
    gemm_k<0, false, false><<<g1, blk>>>(cl2_w, 128, h, cl2_b,
        nullptr, nullptr, nullptr, nullptr,
        x2, nullptr, 0, nullptr, nullptr);

    // logits + fused argmax -> inds, mask -> out[N..2N)
    gemm_k<2, false, false><<<g1, blk>>>(cl3_w, 128, x2, cl3_b,
        nullptr, nullptr, nullptr, nullptr,
        nullptr, nullptr, 0, inds, out + N_PIX);

    // y_all (HMMA) + fused regression -> x_real
    yall_mma<<<N_PIX / 128, 512, YA_SMEM_TOTAL>>>(catT, w2b, b2, inds, w3, b3, out);
}

// round 5
// speedup vs baseline: 1.7062x; 1.0017x over previous
#include <cuda_runtime.h>
#include <cuda_bf16.h>
#include <cstdint>

// ---------------------------------------------------------------------------
// Problem constants
// ---------------------------------------------------------------------------
#define N_PIX   131072      // 16 * 8192 pixels
#define W_PIX   8192
#define EPS_BN  1e-5f

// ---------------------------------------------------------------------------
// Device scratch (static; no cudaMalloc allowed)
// ---------------------------------------------------------------------------
__device__ float          g_h[128 * N_PIX];            // lrelu(bn(cl1.x)) channel-major
__device__ float          g_x2[128 * N_PIX];           // lrelu(cl2.h)     channel-major
__device__ __nv_bfloat16  g_catT[(size_t)N_PIX * 256]; // pixel-major [n][0:128]=r [128:256]=h
__device__ __nv_bfloat16  g_w2b[256 * 256];            // bf16 W2cat[s*32+o][f]
__device__ int            g_inds[N_PIX];

__device__ __forceinline__ float lrelu_f(float v) { return v >= 0.f ? v : 0.01f * v; }

__device__ __forceinline__ uint32_t smem_u32(const void* p) {
    uint32_t a;
    asm("{ .reg .u64 t; cvta.to.shared.u64 t, %1; cvt.u32.u64 %0, t; }" : "=r"(a) : "l"(p));
    return a;
}

#define CP_ASYNC16(dst, src) \
    asm volatile("cp.async.cg.shared.global [%0], [%1], 16;" :: "r"(dst), "l"(src) : "memory")
#define CP_COMMIT()  asm volatile("cp.async.commit_group;" ::: "memory")
#define CP_WAIT0()   asm volatile("cp.async.wait_group 0;" ::: "memory")

#define LDSM_X4(r, addr) \
    asm volatile("ldmatrix.sync.aligned.m8n8.x4.shared.b16 {%0,%1,%2,%3}, [%4];" \
        : "=r"((r)[0]), "=r"((r)[1]), "=r"((r)[2]), "=r"((r)[3]) : "r"(addr))
#define LDSM_X2(r, addr) \
    asm volatile("ldmatrix.sync.aligned.m8n8.x2.shared.b16 {%0,%1}, [%2];" \
        : "=r"((r)[0]), "=r"((r)[1]) : "r"(addr))
#define MMA16816(d, a, b) \
    asm volatile("mma.sync.aligned.m16n8k16.row.col.f32.bf16.bf16.f32 " \
        "{%0,%1,%2,%3},{%4,%5,%6,%7},{%8,%9},{%0,%1,%2,%3};" \
        : "+f"((d)[0]), "+f"((d)[1]), "+f"((d)[2]), "+f"((d)[3]) \
        : "r"((a)[0]), "r"((a)[1]), "r"((a)[2]), "r"((a)[3]), "r"((b)[0]), "r"((b)[1]))

// ---------------------------------------------------------------------------
// prep: build bf16 W2cat[s*32+o][f] = w2[s][f][o]
// ---------------------------------------------------------------------------
__global__ void prep_w2(const float* __restrict__ w2, __nv_bfloat16* __restrict__ w2b) {
    int idx = blockIdx.x * 256 + threadIdx.x;   // 0..65535
    int so = idx >> 8;
    int f  = idx & 255;
    int s  = so >> 5;
    int o  = so & 31;
    w2b[so * 256 + f] = __float2bfloat16(w2[(s * 256 + f) * 32 + o]);
}

// ---------------------------------------------------------------------------
// fp32 register-tiled GEMM, 128 out x 128 px tile, BK=16, 256 threads.
// Thread pixel map: j<4 -> cg*4+j ; j>=4 -> 64+cg*4+(j-4)  (conflict-free LDS)
// MODE 0: store fp32 (channel-major) and/or bf16 catT (pixel-major at bfOff)
// MODE 2: fused argmax -> indsOut, mask channel (row 128 of W) -> maskOut
// ---------------------------------------------------------------------------
template<int MODE, bool XIN, bool BN>
__global__ __launch_bounds__(256, 2) void gemm_k(
    const float* __restrict__ W, int K,
    const float* __restrict__ X,
    const float* __restrict__ bias,
    const float* __restrict__ bng, const float* __restrict__ bnb,
    const float* __restrict__ bnm, const float* __restrict__ bnv,
    float* __restrict__ outF32,
    __nv_bfloat16* __restrict__ outBf, int bfOff,
    int* __restrict__ indsOut,
    float* __restrict__ maskOut)
{
    __shared__ float sX[16][128];
    __shared__ float sW[16][128];

    const int tid = threadIdx.x;
    const int rg = tid >> 4;          // channel group (8 channels)
    const int cg = tid & 15;          // pixel group
    const int n0 = blockIdx.x * 128;

    const int xstride = XIN ? W_PIX : N_PIX;
    const int xbase   = XIN ? ((n0 >> 13) * (128 * W_PIX) + (n0 & (W_PIX - 1))) : n0;

    const int lr = tid >> 4;
    const int lc = (tid & 15) * 8;
    const int wo = tid & 127;
    const int wk = (tid >> 7) * 8;

    float acc[8][8];
#pragma unroll
    for (int i = 0; i < 8; i++)
#pragma unroll
        for (int j = 0; j < 8; j++) acc[i][j] = 0.f;

    float maskAcc = 0.f;
    __shared__ float swm[128];
    if (MODE == 2) {
        if (tid < 128) swm[tid] = W[128 * 128 + tid];
    }

    for (int k0 = 0; k0 < K; k0 += 16) {
        const float* xg = X + xbase + (k0 + lr) * xstride + lc;
        float4 xv0 = *(const float4*)(xg);
        float4 xv1 = *(const float4*)(xg + 4);
        const float* wg = W + wo * K + k0 + wk;
        float4 wv0 = *(const float4*)(wg);
        float4 wv1 = *(const float4*)(wg + 4);

        __syncthreads();
        *(float4*)&sX[lr][lc]     = xv0;
        *(float4*)&sX[lr][lc + 4] = xv1;
        sW[wk + 0][wo] = wv0.x; sW[wk + 1][wo] = wv0.y;
        sW[wk + 2][wo] = wv0.z; sW[wk + 3][wo] = wv0.w;
        sW[wk + 4][wo] = wv1.x; sW[wk + 5][wo] = wv1.y;
        sW[wk + 6][wo] = wv1.z; sW[wk + 7][wo] = wv1.w;
        __syncthreads();

#pragma unroll
        for (int kk = 0; kk < 16; kk++) {
            float4 xa = *(const float4*)&sX[kk][cg * 4];        // contiguous across lanes
            float4 xb = *(const float4*)&sX[kk][64 + cg * 4];   // contiguous across lanes
            float4 wa = *(const float4*)&sW[kk][rg * 8];
            float4 wb = *(const float4*)&sW[kk][rg * 8 + 4];
            float xr[8] = {xa.x, xa.y, xa.z, xa.w, xb.x, xb.y, xb.z, xb.w};
            float wr[8] = {wa.x, wa.y, wa.z, wa.w, wb.x, wb.y, wb.z, wb.w};
#pragma unroll
            for (int i = 0; i < 8; i++)
#pragma unroll
                for (int j = 0; j < 8; j++)
                    acc[i][j] = fmaf(wr[i], xr[j], acc[i][j]);
        }

        if (MODE == 2) {
            if (tid < 128) {
#pragma unroll
                for (int kk = 0; kk < 16; kk++)
                    maskAcc = fmaf(swm[k0 + kk], sX[kk][tid], maskAcc);
            }
        }
    }

    float al[8], be[8];
#pragma unroll
    for (int i = 0; i < 8; i++) {
        int o = rg * 8 + i;
        float b = bias ? bias[o] : 0.f;
        if (BN) {
            float sc = bng[o] * rsqrtf(bnv[o] + EPS_BN);
            al[i] = sc;
            be[i] = (b - bnm[o]) * sc + bnb[o];
        } else {
            al[i] = 1.f;
            be[i] = b;
        }
    }

    if (MODE == 2) {
        __syncthreads();
        float (*redv)[128] = sX;
        int   (*redi)[128] = (int (*)[128])sW;
#pragma unroll
        for (int j = 0; j < 8; j++) {
            int px = (j < 4) ? (cg * 4 + j) : (64 + cg * 4 + j - 4);
            float bv = -3.4e38f;
            int bi = 0;
#pragma unroll
            for (int i = 0; i < 8; i++) {
                float v = fmaf(al[i], acc[i][j], be[i]);
                if (v > bv) { bv = v; bi = rg * 8 + i; }
            }
            redv[rg][px] = bv;
            redi[rg][px] = bi;
        }
        __syncthreads();
        if (tid < 128) {
            float bv = redv[0][tid];
            int bi = redi[0][tid];
#pragma unroll
            for (int g = 1; g < 16; g++) {
                float v = redv[g][tid];
                if (v > bv) { bv = v; bi = redi[g][tid]; }
            }
            indsOut[n0 + tid] = bi;
            maskOut[n0 + tid] = lrelu_f(maskAcc + bias[128]);
        }
        return;
    }

    // MODE 0
    if (outF32) {
#pragma unroll
        for (int i = 0; i < 8; i++) {
            float* p = outF32 + (size_t)(rg * 8 + i) * N_PIX + n0;
            float v[8];
#pragma unroll
            for (int j = 0; j < 8; j++) v[j] = lrelu_f(fmaf(al[i], acc[i][j], be[i]));
            *(float4*)(p + cg * 4)      = make_float4(v[0], v[1], v[2], v[3]);
            *(float4*)(p + 64 + cg * 4) = make_float4(v[4], v[5], v[6], v[7]);
        }
    }
    if (outBf) {
        const int c0 = rg * 8;
#pragma unroll
        for (int j = 0; j < 8; j++) {
            int px = (j < 4) ? (cg * 4 + j) : (64 + cg * 4 + j - 4);
            float v[8];
#pragma unroll
            for (int i = 0; i < 8; i++) v[i] = lrelu_f(fmaf(al[i], acc[i][j], be[i]));
            __nv_bfloat162 p0 = __floats2bfloat162_rn(v[0], v[1]);
            __nv_bfloat162 p1 = __floats2bfloat162_rn(v[2], v[3]);
            __nv_bfloat162 p2 = __floats2bfloat162_rn(v[4], v[5]);
            __nv_bfloat162 p3 = __floats2bfloat162_rn(v[6], v[7]);
            uint4 pk = make_uint4(*(uint32_t*)&p0, *(uint32_t*)&p1,
                                  *(uint32_t*)&p2, *(uint32_t*)&p3);
            *(uint4*)(outBf + (size_t)(n0 + px) * 256 + bfOff + c0) = pk;
        }
    }
}

// ---------------------------------------------------------------------------
// y_all via warp-level bf16 mma.sync (sm_100-safe HMMA path)
// Block: 128 px x 256 out, 512 threads = 16 warps (4x4), warp tile 32px x 64out.
// K=256 in 8 cp.async double-buffered stages of BK=32.
// Smem rows padded to 40 halves (80B) -> conflict-free ldmatrix.
// Fused epilogue: per-pixel super select, lrelu(+b2), dot w3, +b3 -> x_real.
// ---------------------------------------------------------------------------
#define YA_STRIDE 40                       // halves per smem row
#define YA_SA_OFF 0                        // 2*128*40*2  = 20480
#define YA_SB_OFF 20480                    // 2*256*40*2  = 40960
#define YA_SI_OFF 61440                    // inds 128*4  = 512
#define YA_SR_OFF 61952                    // red  128*4  = 512
#define YA_SW3_OFF 62464                   // w3   128*32*4 = 16384
#define YA_SB2_OFF 78848                   // b2   256*4  = 1024
#define YA_SMEM_TOTAL 79872

__global__ __launch_bounds__(512, 1) void yall_mma(
    const __nv_bfloat16* __restrict__ catT,
    const __nv_bfloat16* __restrict__ w2b,
    const float* __restrict__ b2,
    const int* __restrict__ inds,
    const float* __restrict__ w3,
    const float* __restrict__ b3,
    float* __restrict__ outX)
{
    extern __shared__ char sm[];
    __nv_bfloat16* sA = (__nv_bfloat16*)(sm + YA_SA_OFF);
    __nv_bfloat16* sB = (__nv_bfloat16*)(sm + YA_SB_OFF);
    int*   sInds = (int*)(sm + YA_SI_OFF);
    float* sRed  = (float*)(sm + YA_SR_OFF);
    float* sW3   = (float*)(sm + YA_SW3_OFF);
    float* sB2   = (float*)(sm + YA_SB2_OFF);

    const int tid  = threadIdx.x;
    const int wid  = tid >> 5;
    const int lane = tid & 31;
    const int mr   = wid >> 2;        // 0..3 : pixel band (32 px)
    const int nc   = wid & 3;         // 0..3 : out band (64 outs)
    const int n0   = blockIdx.x * 128;

    const uint32_t sAu = smem_u32(sA);
    const uint32_t sBu = smem_u32(sB);

    if (tid < 128) { sInds[tid] = inds[n0 + tid]; sRed[tid] = 0.f; }
    if (tid < 256) sB2[tid] = b2[tid];
    __syncthreads();
    {   // gather w3 rows for this tile's pixels
        int px = tid >> 2, q = tid & 3;
        int ind = sInds[px];
        *(float4*)&sW3[px * 32 + q * 8]     = *(const float4*)&w3[ind * 32 + q * 8];
        *(float4*)&sW3[px * 32 + q * 8 + 4] = *(const float4*)&w3[ind * 32 + q * 8 + 4];
    }

    // stage loaders: A 128x32 (512 x 16B), B 256x32 (1024 x 16B)
    const int aRow = tid >> 2, aSeg = tid & 3;
    auto loadStage = [&](int ks, int buf) {
        int k0 = ks * 32;
        CP_ASYNC16(sAu + ((buf * 128 + aRow) * YA_STRIDE + aSeg * 8) * 2,
                   catT + (size_t)(n0 + aRow) * 256 + k0 + aSeg * 8);
#pragma unroll
        for (int i = 0; i < 2; i++) {
            int idx = tid + i * 512;
            int row = idx >> 2, seg = idx & 3;
            CP_ASYNC16(sBu + ((buf * 256 + row) * YA_STRIDE + seg * 8) * 2,
                       w2b + row * 256 + k0 + seg * 8);
        }
    };

    float acc[2][8][4];
#pragma unroll
    for (int mt = 0; mt < 2; mt++)
#pragma unroll
        for (int nt = 0; nt < 8; nt++)
#pragma unroll
            for (int q = 0; q < 4; q++) acc[mt][nt][q] = 0.f;

    loadStage(0, 0);
    CP_COMMIT();

    // per-lane ldmatrix address components (bytes)
    const uint32_t aLane = (uint32_t)((lane & 15) * YA_STRIDE + (lane >> 4) * 8) * 2;
    const uint32_t bLane = (uint32_t)((lane & 7) * YA_STRIDE + ((lane >> 3) & 1) * 8) * 2;

#pragma unroll 1
    for (int ks = 0; ks < 8; ks++) {
        int buf = ks & 1;
        CP_WAIT0();
        __syncthreads();
        if (ks < 7) { loadStage(ks + 1, buf ^ 1); CP_COMMIT(); }

        uint32_t aBase = sAu + (uint32_t)((buf * 128 + mr * 32) * YA_STRIDE) * 2 + aLane;
        uint32_t bBase = sBu + (uint32_t)((buf * 256 + nc * 64) * YA_STRIDE) * 2 + bLane;
#pragma unroll
        for (int kf = 0; kf < 2; kf++) {
            uint32_t a[2][4];
#pragma unroll
            for (int mt = 0; mt < 2; mt++)
                LDSM_X4(a[mt], aBase + (uint32_t)(mt * 16 * YA_STRIDE + kf * 16) * 2);
            uint32_t bfr[8][2];
#pragma unroll
            for (int nt = 0; nt < 8; nt++)
                LDSM_X2(bfr[nt], bBase + (uint32_t)(nt * 8 * YA_STRIDE + kf * 16) * 2);
#pragma unroll
            for (int mt = 0; mt < 2; mt++)
#pragma unroll
                for (int nt = 0; nt < 8; nt++)
                    MMA16816(acc[mt][nt], a[mt], bfr[nt]);
        }
    }

    // fused epilogue: super-select + w3 dot, smem atomic reduction per pixel
    const int g = lane >> 2, tc = lane & 3;
#pragma unroll
    for (int mt = 0; mt < 2; mt++) {
#pragma unroll
        for (int rr = 0; rr < 2; rr++) {
            int px = mr * 32 + mt * 16 + g + rr * 8;
            int ind = sInds[px];
            int s = ind >> 4;                 // CLASS_FACTOR = 16
            if ((s >> 1) == nc) {
                int sl = s & 1;
                float part = 0.f;
#pragma unroll
                for (int t = 0; t < 4; t++) {
                    int nt = sl * 4 + t;
#pragma unroll
                    for (int cc = 0; cc < 2; cc++) {
                        int ob  = nt * 8 + tc * 2 + cc;      // out within 64-band
                        int out = nc * 64 + ob;              // global out = s*32 + orel
                        int orel = ob - sl * 32;
                        float y = lrelu_f(acc[mt][nt][rr * 2 + cc] + sB2[out]);
                        part = fmaf(y, sW3[px * 32 + orel], part);
                    }
                }
                atomicAdd(&sRed[px], part);
            }
        }
    }
    __syncthreads();
    if (tid < 128) {
        int ind = sInds[tid];
        outX[n0 + tid] = ((float)ind + sRed[tid] + b3[ind]) * (1.0f / 128.0f);
    }
}

// ---------------------------------------------------------------------------
// Launch
// ---------------------------------------------------------------------------
extern "C" void kernel_launch(void* const* d_in, const int* in_sizes, int n_in,
                              void* d_out, int out_size)
{
    const float* x_in     = (const float*)d_in[0];
    const float* cl1_w    = (const float*)d_in[1];
    const float* cl1_b    = (const float*)d_in[2];
    const float* cl1_bn_g = (const float*)d_in[3];
    const float* cl1_bn_b = (const float*)d_in[4];
    const float* cl1_bn_m = (const float*)d_in[5];
    const float* cl1_bn_v = (const float*)d_in[6];
    const float* cl2_w    = (const float*)d_in[7];
    const float* cl2_b    = (const float*)d_in[8];
    const float* cl3_w    = (const float*)d_in[9];
    const float* cl3_b    = (const float*)d_in[10];
    const float* reg1_w   = (const float*)d_in[11];
    const float* reg1_b   = (const float*)d_in[12];
    const float* reg1_bn_g= (const float*)d_in[13];
    const float* reg1_bn_b= (const float*)d_in[14];
    const float* reg1_bn_m= (const float*)d_in[15];
    const float* reg1_bn_v= (const float*)d_in[16];
    const float* w2       = (const float*)d_in[17];
    const float* b2       = (const float*)d_in[18];
    const float* w3       = (const float*)d_in[19];
    const float* b3       = (const float*)d_in[20];

    float* out = (float*)d_out;          // [0..N) x_real, [N..2N) mask

    float *h, *x2;
    __nv_bfloat16 *catT, *w2b;
    int* inds;
    cudaGetSymbolAddress((void**)&h,    g_h);
    cudaGetSymbolAddress((void**)&x2,   g_x2);
    cudaGetSymbolAddress((void**)&catT, g_catT);
    cudaGetSymbolAddress((void**)&w2b,  g_w2b);
    cudaGetSymbolAddress((void**)&inds, g_inds);

    cudaFuncSetAttribute(yall_mma, cudaFuncAttributeMaxDynamicSharedMemorySize,
                         YA_SMEM_TOTAL);

    const dim3 blk(256);
    const dim3 g1(N_PIX / 128, 1);

    // W2cat -> bf16
    prep_w2<<<256, blk>>>(w2, w2b);

    // h = lrelu(bn(cl1_w . x)) -> fp32 h + bf16 catT[:,128:256]
    gemm_k<0, true, true><<<g1, blk>>>(cl1_w, 128, x_in, cl1_b,
        cl1_bn_g, cl1_bn_b, cl1_bn_m, cl1_bn_v,
        h, catT, 128, nullptr, nullptr);

    // r = lrelu(bn(reg1_w . x)) -> bf16 catT[:,0:128] only
    gemm_k<0, true, true><<<g1, blk>>>(reg1_w, 128, x_in, reg1_b,
        reg1_bn_g, reg1_bn_b, reg1_bn_m, reg1_bn_v,
        nullptr, catT, 0, nullptr, nullptr);

    // x2 = lrelu(cl2_w . h)
    gemm_k<0, false, false><<<g1, blk>>>(cl2_w, 128, h, cl2_b,
        nullptr, nullptr, nullptr, nullptr,
        x2, nullptr, 0, nullptr, nullptr);

    // logits + fused argmax -> inds, mask -> out[N..2N)
    gemm_k<2, false, false><<<g1, blk>>>(cl3_w, 128, x2, cl3_b,
        nullptr, nullptr, nullptr, nullptr,
        nullptr, nullptr, 0, inds, out + N_PIX);

    // y_all (HMMA) + fused regression -> x_real
    yall_mma<<<N_PIX / 128, 512, YA_SMEM_TOTAL>>>(catT, w2b, b2, inds, w3, b3, out);
}

// round 8
// speedup vs baseline: 2.8546x; 1.6730x over previous
#include <cuda_runtime.h>
#include <cuda_fp16.h>
#include <cstdint>

#define N_PIX 131072
#define W_PIX 8192
#define EPS_BN 1e-5f
#define SB128 272
#define SB256 528

// ------------------------- device scratch -------------------------
__device__ __half g_xHi[(size_t)N_PIX * 128];
__device__ __half g_xLo[(size_t)N_PIX * 128];
__device__ __half g_catHi[(size_t)N_PIX * 256];  // [n][0:128)=r, [128:256)=h
__device__ __half g_hLo[(size_t)N_PIX * 128];
__device__ __half g_bfHi[256 * 128], g_bfLo[256 * 128];   // rows 0-127 reg1, 128-255 cl1
__device__ __half g_bmHi[128 * 128], g_bmLo[128 * 128];   // cl2
__device__ __half g_bcHi[128 * 128], g_bcLo[128 * 128];   // cl3[0:128]
__device__ __half g_w2h[256 * 256];                       // w2cat[s*32+o][f]
__device__ float  g_alphaF[256], g_betaF[256];
__device__ int    g_inds[N_PIX];

__device__ __forceinline__ float lrelu_f(float v) { return v >= 0.f ? v : 0.01f * v; }
__device__ __forceinline__ uint32_t smem_u32(const void* p) {
    uint32_t a;
    asm("{ .reg .u64 t; cvta.to.shared.u64 t, %1; cvt.u32.u64 %0, t; }" : "=r"(a) : "l"(p));
    return a;
}
__device__ __forceinline__ uint32_t ford(float f) {
    uint32_t u = __float_as_uint(f);
    return (u & 0x80000000u) ? ~u : (u | 0x80000000u);
}

#define CP_ASYNC16(dst, src) \
    asm volatile("cp.async.cg.shared.global [%0], [%1], 16;" :: "r"(dst), "l"(src) : "memory")
#define CP_COMMIT() asm volatile("cp.async.commit_group;" ::: "memory")
#define CP_WAIT0()  asm volatile("cp.async.wait_group 0;" ::: "memory")
#define LDSM_X4(r, addr) \
    asm volatile("ldmatrix.sync.aligned.m8n8.x4.shared.b16 {%0,%1,%2,%3}, [%4];" \
        : "=r"((r)[0]), "=r"((r)[1]), "=r"((r)[2]), "=r"((r)[3]) : "r"(addr))
#define MMAF16(d, a, b) \
    asm volatile("mma.sync.aligned.m16n8k16.row.col.f32.f16.f16.f32 " \
        "{%0,%1,%2,%3},{%4,%5,%6,%7},{%8,%9},{%0,%1,%2,%3};" \
        : "+f"((d)[0]), "+f"((d)[1]), "+f"((d)[2]), "+f"((d)[3]) \
        : "r"((a)[0]), "r"((a)[1]), "r"((a)[2]), "r"((a)[3]), "r"((b)[0]), "r"((b)[1]))

// warp tile 16px x 64out over KH k, full-K-resident smem, optional 3-product split
template<int KH, int SB, bool P3>
__device__ __forceinline__ void run_pass(float (&acc)[8][4],
    uint32_t aHiB, uint32_t aLoB, uint32_t bHiB, uint32_t bLoB, int lane)
{
    const uint32_t aOff = (uint32_t)((lane & 15) * SB + (lane >> 4) * 16);
    const uint32_t bOff = (uint32_t)(((lane & 7) + ((lane >> 4) & 1) * 8) * SB +
                                     ((lane >> 3) & 1) * 16);
#pragma unroll
    for (int kk = 0; kk < KH / 16; kk++) {
        uint32_t ah[4], al[4];
        LDSM_X4(ah, aHiB + aOff + kk * 32);
        if (P3) LDSM_X4(al, aLoB + aOff + kk * 32);
#pragma unroll
        for (int np = 0; np < 4; np++) {
            uint32_t bh[4];
            LDSM_X4(bh, bHiB + bOff + (uint32_t)(np * 16 * SB) + kk * 32);
            MMAF16(acc[np * 2],     ah, bh);
            MMAF16(acc[np * 2 + 1], ah, bh + 2);
            if (P3) {
                uint32_t bl[4];
                LDSM_X4(bl, bLoB + bOff + (uint32_t)(np * 16 * SB) + kk * 32);
                MMAF16(acc[np * 2],     ah, bl);
                MMAF16(acc[np * 2 + 1], ah, bl + 2);
                MMAF16(acc[np * 2],     al, bh);
                MMAF16(acc[np * 2 + 1], al, bh + 2);
            }
        }
    }
}

// cp.async tile loader: rows x 128 halves, smem stride SB128
__device__ __forceinline__ void cp_tile(uint32_t dst, const __half* src,
                                        int rows, int gHalves, int tid)
{
    int total = rows * 16;
    for (int i = tid; i < total; i += 512) {
        int r = i >> 4, s = i & 15;
        CP_ASYNC16(dst + (uint32_t)(r * SB128 + s * 16), src + (size_t)r * gHalves + s * 8);
    }
}
// rows x 256 halves, stride SB256
__device__ __forceinline__ void cp_tile256(uint32_t dst, const __half* src,
                                           int rows, int tid)
{
    int total = rows * 32;
    for (int i = tid; i < total; i += 512) {
        int r = i >> 5, s = i & 31;
        CP_ASYNC16(dst + (uint32_t)(r * SB256 + s * 16), src + (size_t)r * 256 + s * 8);
    }
}

// ------------------------- prep kernels -------------------------
__global__ void prep_w(const float* __restrict__ cl1_w, const float* __restrict__ reg1_w,
                       const float* __restrict__ cl2_w, const float* __restrict__ cl3_w,
                       const float* __restrict__ w2,
                       const float* cl1_b, const float* cl1_g, const float* cl1_bt,
                       const float* cl1_m, const float* cl1_v,
                       const float* reg1_b, const float* reg1_g, const float* reg1_bt,
                       const float* reg1_m, const float* reg1_v)
{
    int idx = blockIdx.x * 256 + threadIdx.x;
    if (idx < 32768) {
        int o = idx >> 7, k = idx & 127;
        float w = (o < 128) ? reg1_w[o * 128 + k] : cl1_w[(o - 128) * 128 + k];
        __half h = __float2half_rn(w);
        g_bfHi[idx] = h; g_bfLo[idx] = __float2half_rn(w - __half2float(h));
    } else if (idx < 49152) {
        int i = idx - 32768;
        float w = cl2_w[i]; __half h = __float2half_rn(w);
        g_bmHi[i] = h; g_bmLo[i] = __float2half_rn(w - __half2float(h));
    } else if (idx < 65536) {
        int i = idx - 49152;
        float w = cl3_w[i]; __half h = __float2half_rn(w);
        g_bcHi[i] = h; g_bcLo[i] = __float2half_rn(w - __half2float(h));
    } else if (idx < 131072) {
        int i = idx - 65536;
        int so = i >> 8, f = i & 255, s = so >> 5, o = so & 31;
        g_w2h[so * 256 + f] = __float2half_rn(w2[(s * 256 + f) * 32 + o]);
    } else if (idx < 131328) {
        int o = idx - 131072;
        if (o < 128) {
            float a = reg1_g[o] * rsqrtf(reg1_v[o] + EPS_BN);
            g_alphaF[o] = a; g_betaF[o] = (reg1_b[o] - reg1_m[o]) * a + reg1_bt[o];
        } else {
            int c = o - 128;
            float a = cl1_g[c] * rsqrtf(cl1_v[c] + EPS_BN);
            g_alphaF[o] = a; g_betaF[o] = (cl1_b[c] - cl1_m[c]) * a + cl1_bt[c];
        }
    }
}

__global__ void prep_x(const float* __restrict__ x)
{
    __shared__ float t[32][33];
    int b = blockIdx.z, w0 = blockIdx.x * 32, c0 = blockIdx.y * 32;
    int tx = threadIdx.x, ty = threadIdx.y;
    const float* src = x + ((size_t)b * 128 + c0) * W_PIX + w0;
#pragma unroll
    for (int i = 0; i < 4; i++)
        t[ty + i * 8][tx] = src[(size_t)(ty + i * 8) * W_PIX + tx];
    __syncthreads();
    size_t nbase = (size_t)b * W_PIX + w0;
#pragma unroll
    for (int i = 0; i < 4; i++) {
        int wl = ty + i * 8;
        float v = t[tx][wl];
        __half h = __float2half_rn(v);
        g_xHi[(nbase + wl) * 128 + c0 + tx] = h;
        g_xLo[(nbase + wl) * 128 + c0 + tx] = __float2half_rn(v - __half2float(h));
    }
}

// ------------------------- front: x -> [r,h] -------------------------
#define F_AHI 0
#define F_ALO 34816
#define F_BHI 69632
#define F_BLO 139264
#define F_TOTAL 208896

__global__ __launch_bounds__(512, 1) void front_kernel()
{
    extern __shared__ char sm[];
    const uint32_t sb = smem_u32(sm);
    const int tid = threadIdx.x, wid = tid >> 5, lane = tid & 31;
    const int mW = wid >> 1, nB = wid & 1;
    const int n0 = blockIdx.x * 128;

    cp_tile(sb + F_AHI, g_xHi + (size_t)n0 * 128, 128, 128, tid);
    cp_tile(sb + F_ALO, g_xLo + (size_t)n0 * 128, 128, 128, tid);
    cp_tile(sb + F_BHI, g_bfHi, 256, 128, tid);
    cp_tile(sb + F_BLO, g_bfLo, 256, 128, tid);
    CP_COMMIT(); CP_WAIT0();
    __syncthreads();

#pragma unroll 1
    for (int pass = 0; pass < 2; pass++) {
        float acc[8][4];
#pragma unroll
        for (int nt = 0; nt < 8; nt++)
#pragma unroll
            for (int q = 0; q < 4; q++) acc[nt][q] = 0.f;
        run_pass<128, SB128, true>(acc,
            sb + F_AHI + mW * 16 * SB128, sb + F_ALO + mW * 16 * SB128,
            sb + F_BHI + (pass * 128 + nB * 64) * SB128,
            sb + F_BLO + (pass * 128 + nB * 64) * SB128, lane);
#pragma unroll
        for (int nt = 0; nt < 8; nt++) {
#pragma unroll
            for (int row = 0; row < 2; row++) {
                int px = mW * 16 + (lane >> 2) + row * 8;
                int og = pass * 128 + nB * 64 + nt * 8 + (lane & 3) * 2;
                float v0 = lrelu_f(g_alphaF[og]     * acc[nt][row * 2]     + g_betaF[og]);
                float v1 = lrelu_f(g_alphaF[og + 1] * acc[nt][row * 2 + 1] + g_betaF[og + 1]);
                __half2 hv = __floats2half2_rn(v0, v1);
                *(__half2*)(g_catHi + (size_t)(n0 + px) * 256 + og) = hv;
                if (pass == 1) {
                    *(__half2*)(g_hLo + (size_t)(n0 + px) * 128 + og - 128) =
                        __floats2half2_rn(v0 - __low2float(hv), v1 - __high2float(hv));
                }
            }
        }
    }
}

// ------------------------- midcls: h -> x2 -> argmax/mask -------------------------
#define M_AHI 0
#define M_ALO 34816
#define M_BMH 69632
#define M_BML 104448
#define M_BCH 139264
#define M_BCL 174080
#define M_KEY 208896
#define M_MW  209920
#define M_TOTAL 210432

__global__ __launch_bounds__(512, 1) void midcls_kernel(
    const float* __restrict__ cl2_b, const float* __restrict__ cl3_w,
    const float* __restrict__ cl3_b, float* __restrict__ maskOut)
{
    extern __shared__ char sm[];
    const uint32_t sb = smem_u32(sm);
    unsigned long long* sKey = (unsigned long long*)(sm + M_KEY);
    float* sMw = (float*)(sm + M_MW);
    const int tid = threadIdx.x, wid = tid >> 5, lane = tid & 31;
    const int mW = wid >> 1, nB = wid & 1;
    const int n0 = blockIdx.x * 128;

    if (tid < 128) { sKey[tid] = 0ull; sMw[tid] = cl3_w[128 * 128 + tid]; }

    cp_tile(sb + M_AHI, g_catHi + (size_t)n0 * 256 + 128, 128, 256, tid);
    cp_tile(sb + M_ALO, g_hLo + (size_t)n0 * 128, 128, 128, tid);
    cp_tile(sb + M_BMH, g_bmHi, 128, 128, tid);
    cp_tile(sb + M_BML, g_bmLo, 128, 128, tid);
    cp_tile(sb + M_BCH, g_bcHi, 128, 128, tid);
    cp_tile(sb + M_BCL, g_bcLo, 128, 128, tid);
    CP_COMMIT(); CP_WAIT0();
    __syncthreads();

    float acc[8][4];
#pragma unroll
    for (int nt = 0; nt < 8; nt++)
#pragma unroll
        for (int q = 0; q < 4; q++) acc[nt][q] = 0.f;
    run_pass<128, SB128, true>(acc,
        sb + M_AHI + mW * 16 * SB128, sb + M_ALO + mW * 16 * SB128,
        sb + M_BMH + nB * 64 * SB128, sb + M_BML + nB * 64 * SB128, lane);
    __syncthreads();                       // all h reads done

    // write x2 hi/lo back over A
#pragma unroll
    for (int nt = 0; nt < 8; nt++) {
#pragma unroll
        for (int row = 0; row < 2; row++) {
            int px = mW * 16 + (lane >> 2) + row * 8;
            int o  = nB * 64 + nt * 8 + (lane & 3) * 2;
            float v0 = lrelu_f(acc[nt][row * 2]     + cl2_b[o]);
            float v1 = lrelu_f(acc[nt][row * 2 + 1] + cl2_b[o + 1]);
            __half2 hv = __floats2half2_rn(v0, v1);
            *(__half2*)(sm + M_AHI + px * SB128 + o * 2) = hv;
            *(__half2*)(sm + M_ALO + px * SB128 + o * 2) =
                __floats2half2_rn(v0 - __low2float(hv), v1 - __high2float(hv));
        }
    }
    __syncthreads();

#pragma unroll
    for (int nt = 0; nt < 8; nt++)
#pragma unroll
        for (int q = 0; q < 4; q++) acc[nt][q] = 0.f;
    run_pass<128, SB128, true>(acc,
        sb + M_AHI + mW * 16 * SB128, sb + M_ALO + mW * 16 * SB128,
        sb + M_BCH + nB * 64 * SB128, sb + M_BCL + nB * 64 * SB128, lane);

    // argmax (first-max-index via 255-o tiebreak)
#pragma unroll
    for (int row = 0; row < 2; row++) {
        int px = mW * 16 + (lane >> 2) + row * 8;
        float bv = -3.4e38f; int bi = 0;
#pragma unroll
        for (int nt = 0; nt < 8; nt++) {
#pragma unroll
            for (int cc = 0; cc < 2; cc++) {
                int o = nB * 64 + nt * 8 + (lane & 3) * 2 + cc;
                float v = acc[nt][row * 2 + cc] + cl3_b[o];
                if (v > bv) { bv = v; bi = o; }
            }
        }
        atomicMax(&sKey[px], ((unsigned long long)ford(bv) << 32) |
                             (unsigned long long)(255 - bi));
    }
    __syncthreads();

    if (tid < 128) {
        int ind = 255 - (int)(sKey[tid] & 0xFFFFFFFFull);
        g_inds[n0 + tid] = ind;
        float m = cl3_b[128];
#pragma unroll 8
        for (int k = 0; k < 128; k++) {
            float xv = __half2float(*(__half*)(sm + M_AHI + tid * SB128 + k * 2)) +
                       __half2float(*(__half*)(sm + M_ALO + tid * SB128 + k * 2));
            m = fmaf(sMw[k], xv, m);
        }
        maskOut[n0 + tid] = lrelu_f(m);
    }
}

// ------------------------- yall: cat . w2cat^T + regression -------------------------
#define Y_A   0
#define Y_B   67584
#define Y_SI  202752
#define Y_SR  203264
#define Y_SB2 203776
#define Y_SW3 204800
#define Y_TOTAL 221184

__global__ __launch_bounds__(512, 1) void yall_kernel(
    const float* __restrict__ b2, const float* __restrict__ w3,
    const float* __restrict__ b3, float* __restrict__ outX)
{
    extern __shared__ char sm[];
    const uint32_t sb = smem_u32(sm);
    int*   sInds = (int*)(sm + Y_SI);
    float* sRed  = (float*)(sm + Y_SR);
    float* sB2   = (float*)(sm + Y_SB2);
    float* sW3   = (float*)(sm + Y_SW3);
    const int tid = threadIdx.x, wid = tid >> 5, lane = tid & 31;
    const int mW = wid >> 1, nB = wid & 1, tc = lane & 3;
    const int n0 = blockIdx.x * 128;

    if (tid < 128) { sInds[tid] = g_inds[n0 + tid]; sRed[tid] = 0.f; }
    if (tid < 256) sB2[tid] = b2[tid];
    cp_tile256(sb + Y_A, g_catHi + (size_t)n0 * 256, 128, tid);
    cp_tile256(sb + Y_B, g_w2h, 256, tid);
    CP_COMMIT();
    __syncthreads();                      // sInds ready
    {
        int px = tid >> 2, q = tid & 3;
        int ind = sInds[px];
        *(float4*)&sW3[px * 32 + q * 8]     = *(const float4*)&w3[ind * 32 + q * 8];
        *(float4*)&sW3[px * 32 + q * 8 + 4] = *(const float4*)&w3[ind * 32 + q * 8 + 4];
    }
    CP_WAIT0();
    __syncthreads();

#pragma unroll 1
    for (int pass = 0; pass < 2; pass++) {
        float acc[8][4];
#pragma unroll
        for (int nt = 0; nt < 8; nt++)
#pragma unroll
            for (int q = 0; q < 4; q++) acc[nt][q] = 0.f;
        run_pass<256, SB256, false>(acc,
            sb + Y_A + mW * 16 * SB256, 0,
            sb + Y_B + (pass * 128 + nB * 64) * SB256, 0, lane);

        int band = pass * 2 + nB;
#pragma unroll
        for (int row = 0; row < 2; row++) {
            int px = mW * 16 + (lane >> 2) + row * 8;
            int ind = sInds[px];
            int s = ind >> 4;
            if ((s >> 1) == band) {
                int sl = s & 1;
                float part = 0.f;
#pragma unroll
                for (int t = 0; t < 4; t++) {
                    int nt = sl * 4 + t;
#pragma unroll
                    for (int cc = 0; cc < 2; cc++) {
                        int out  = pass * 128 + nB * 64 + nt * 8 + tc * 2 + cc;
                        int orel = t * 8 + tc * 2 + cc;
                        float y = lrelu_f(acc[nt][row * 2 + cc] + sB2[out]);
                        part = fmaf(y, sW3[px * 32 + orel], part);
                    }
                }
                atomicAdd(&sRed[px], part);
            }
        }
    }
    __syncthreads();
    if (tid < 128) {
        int ind = sInds[tid];
        outX[n0 + tid] = ((float)ind + sRed[tid] + b3[ind]) * (1.0f / 128.0f);
    }
}

// ------------------------- launch -------------------------
extern "C" void kernel_launch(void* const* d_in, const int* in_sizes, int n_in,
                              void* d_out, int out_size)
{
    const float* x_in     = (const float*)d_in[0];
    const float* cl1_w    = (const float*)d_in[1];
    const float* cl1_b    = (const float*)d_in[2];
    const float* cl1_bn_g = (const float*)d_in[3];
    const float* cl1_bn_b = (const float*)d_in[4];
    const float* cl1_bn_m = (const float*)d_in[5];
    const float* cl1_bn_v = (const float*)d_in[6];
    const float* cl2_w    = (const float*)d_in[7];
    const float* cl2_b    = (const float*)d_in[8];
    const float* cl3_w    = (const float*)d_in[9];
    const float* cl3_b    = (const float*)d_in[10];
    const float* reg1_w   = (const float*)d_in[11];
    const float* reg1_b   = (const float*)d_in[12];
    const float* reg1_bn_g= (const float*)d_in[13];
    const float* reg1_bn_b= (const float*)d_in[14];
    const float* reg1_bn_m= (const float*)d_in[15];
    const float* reg1_bn_v= (const float*)d_in[16];
    const float* w2       = (const float*)d_in[17];
    const float* b2       = (const float*)d_in[18];
    const float* w3       = (const float*)d_in[19];
    const float* b3       = (const float*)d_in[20];

    float* out = (float*)d_out;          // [0..N) x_real, [N..2N) mask

    cudaFuncSetAttribute(front_kernel, cudaFuncAttributeMaxDynamicSharedMemorySize, F_TOTAL);
    cudaFuncSetAttribute(midcls_kernel, cudaFuncAttributeMaxDynamicSharedMemorySize, M_TOTAL);
    cudaFuncSetAttribute(yall_kernel, cudaFuncAttributeMaxDynamicSharedMemorySize, Y_TOTAL);

    prep_w<<<513, 256>>>(cl1_w, reg1_w, cl2_w, cl3_w, w2,
                         cl1_b, cl1_bn_g, cl1_bn_b, cl1_bn_m, cl1_bn_v,
                         reg1_b, reg1_bn_g, reg1_bn_b, reg1_bn_m, reg1_bn_v);
    prep_x<<<dim3(W_PIX / 32, 4, 16), dim3(32, 8)>>>(x_in);
    front_kernel<<<N_PIX / 128, 512, F_TOTAL>>>();
    midcls_kernel<<<N_PIX / 128, 512, M_TOTAL>>>(cl2_b, cl3_w, cl3_b, out + N_PIX);
    yall_kernel<<<N_PIX / 128, 512, Y_TOTAL>>>(b2, w3, b3, out);
}